// round 2
// baseline (speedup 1.0000x reference)
#include <cuda_runtime.h>

#define MAXN 50000
#define MAXE 600000
#define LN_EPS 1e-5f

// ---------------- static device scratch (no runtime allocation) ----------------
__device__ int    g_is64_e, g_is64_b;
__device__ int    g_deg[MAXN];
__device__ int    g_rowstart[MAXN];
__device__ int    g_cursor[MAXN];
__device__ float  g_invdeg[MAXN];
__device__ int    g_csr[MAXE];
__device__ float4 g_agg[MAXN * 32];   // [N,128] mean-aggregated features
__device__ float4 g_h0[MAXN * 32];    // layer0 out [N,128]
__device__ float4 g_h1[MAXN * 32];    // layer1 out [N,128]
__device__ float4 g_h2[MAXN * 16];    // layer2 out [N,64]
__device__ float  g_psum[64 * 64];
__device__ int    g_pmax[64 * 64];
__device__ int    g_pcnt[64];

__device__ __forceinline__ long long ld_idx(const void* p, long long i, int is64) {
    return is64 ? ((const long long*)p)[i] : (long long)((const int*)p)[i];
}

__device__ __forceinline__ void ffma2(unsigned long long& d, unsigned long long a, unsigned long long b) {
    asm("fma.rn.f32x2 %0, %1, %2, %0;" : "+l"(d) : "l"(a), "l"(b));
}

// ---------------- dtype width detection (int64 vs int32 indices) ----------------
__global__ void k_detect(const void* ei, long long ecnt, const void* bat, long long bcnt, int N) {
    __shared__ int ok_e, ok_b;
    int tid = threadIdx.x;
    if (tid == 0) { ok_e = 1; ok_b = 1; }
    __syncthreads();
    long long ne = ecnt / 2;   // int64 entries safely readable even if data is int32
    long long nb = bcnt / 2;
    for (int i = tid; i < 1024; i += blockDim.x) {
        long long ie = (ne - 1) * (long long)i / 1023;
        long long v = ((const long long*)ei)[ie];
        if (v < 0 || v >= (long long)N) atomicAnd(&ok_e, 0);
        long long ib = (nb - 1) * (long long)i / 1023;
        long long w = ((const long long*)bat)[ib];
        if (w < 0 || w >= 64) atomicAnd(&ok_b, 0);
    }
    __syncthreads();
    if (tid == 0) { g_is64_e = ok_e; g_is64_b = ok_b; }
}

// ---------------- CSR build ----------------
__global__ void k_zero(int N) {
    int i = blockIdx.x * blockDim.x + threadIdx.x;
    if (i < N) g_deg[i] = 0;
    if (i < 64 * 64) { g_psum[i] = 0.f; g_pmax[i] = 0; }
    if (i < 64) g_pcnt[i] = 0;
}

__global__ void k_count(const void* ei, int E) {
    int is64 = g_is64_e;
    int e = blockIdx.x * blockDim.x + threadIdx.x;
    if (e >= E) return;
    int d = (int)ld_idx(ei, (long long)E + e, is64);
    atomicAdd(&g_deg[d], 1);
}

__global__ void k_scan(int N) {
    __shared__ int wsum[32];
    __shared__ int s_carry;
    int tid = threadIdx.x, lane = tid & 31, wid = tid >> 5;
    if (tid == 0) s_carry = 0;
    for (int base = 0; base < N; base += 1024) {
        __syncthreads();
        int carry = s_carry;
        int i = base + tid;
        int v = (i < N) ? g_deg[i] : 0;
        int x = v;
#pragma unroll
        for (int o = 1; o < 32; o <<= 1) { int y = __shfl_up_sync(0xffffffffu, x, o); if (lane >= o) x += y; }
        if (lane == 31) wsum[wid] = x;
        __syncthreads();
        if (wid == 0) {
            int w = wsum[lane];
#pragma unroll
            for (int o = 1; o < 32; o <<= 1) { int y = __shfl_up_sync(0xffffffffu, w, o); if (lane >= o) w += y; }
            wsum[lane] = w;
        }
        __syncthreads();
        int prefix = carry + (wid ? wsum[wid - 1] : 0) + (x - v);
        if (i < N) {
            g_rowstart[i] = prefix;
            g_cursor[i] = prefix;
            g_invdeg[i] = 1.0f / fmaxf((float)v, 1.0f);
        }
        __syncthreads();
        if (tid == 0) s_carry = carry + wsum[31];
    }
}

__global__ void k_fill(const void* ei, int E) {
    int is64 = g_is64_e;
    int e = blockIdx.x * blockDim.x + threadIdx.x;
    if (e >= E) return;
    int s = (int)ld_idx(ei, e, is64);
    int d = (int)ld_idx(ei, (long long)E + e, is64);
    int pos = atomicAdd(&g_cursor[d], 1);
    g_csr[pos] = s;
}

// ---------------- mean aggregation: one warp per node ----------------
__global__ void k_agg(const float4* __restrict__ feat, float4* __restrict__ agg, int N) {
    int node = (blockIdx.x * blockDim.x + threadIdx.x) >> 5;
    int lane = threadIdx.x & 31;
    if (node >= N) return;
    int start = g_rowstart[node], dg = g_deg[node];
    float4 acc = make_float4(0.f, 0.f, 0.f, 0.f);
    int j = 0;
    for (; j + 1 < dg; j += 2) {
        int s0 = g_csr[start + j];
        int s1 = g_csr[start + j + 1];
        float4 v0 = feat[s0 * 32 + lane];
        float4 v1 = feat[s1 * 32 + lane];
        acc.x += v0.x + v1.x; acc.y += v0.y + v1.y;
        acc.z += v0.z + v1.z; acc.w += v0.w + v1.w;
    }
    if (j < dg) {
        int s0 = g_csr[start + j];
        float4 v0 = feat[s0 * 32 + lane];
        acc.x += v0.x; acc.y += v0.y; acc.z += v0.z; acc.w += v0.w;
    }
    float inv = g_invdeg[node];
    acc.x *= inv; acc.y *= inv; acc.z *= inv; acc.w *= inv;
    agg[node * 32 + lane] = acc;
}

// ---------------- fused dual-GEMM + bias + LayerNorm + ReLU ----------------
// h[n,o] = sum_k X[n,k]*Wr[o,k] + sum_k AGG[n,k]*Wl[o,k] + bl[o]; LN over o; relu.
// Tile: 64 nodes x OUT cols, K=256 (X cols 0..127 | AGG cols 128..255), f32x2 packed FMA.
template <int OUT>
__global__ __launch_bounds__(256, 1) void k_combine(
    const float4* __restrict__ X, const float4* __restrict__ A,
    const float* __restrict__ Wl, const float* __restrict__ Wr,
    const float* __restrict__ bl, const float* __restrict__ gam, const float* __restrict__ bet,
    float* __restrict__ out, int N)
{
    constexpr int WSS = OUT + 2;   // float2 stride of W smem rows (16B-aligned for float4 reads)
    constexpr int CPT = OUT / 16;  // cols per thread
    extern __shared__ unsigned char smem[];
    float2* Ws = reinterpret_cast<float2*>(smem);            // [128][WSS] : (Wt[2kk][o], Wt[2kk+1][o])
    float2* As = Ws + 128 * WSS;                             // [64][129]  : (in[n][2kk], in[n][2kk+1])
    float* aux = reinterpret_cast<float*>(As + 64 * 129);
    float* blsh = aux;
    float* gsh  = aux + OUT;
    float* bsh  = aux + 2 * OUT;

    int tid = threadIdx.x;

    // stage weights: k<128 -> Wr (pairs with X), k>=128 -> Wl (pairs with AGG)
    const float2* Wr2 = reinterpret_cast<const float2*>(Wr);
    const float2* Wl2 = reinterpret_cast<const float2*>(Wl);
    for (int idx = tid; idx < OUT * 64; idx += 256) {
        int o = idx >> 6, kp = idx & 63;
        Ws[kp * WSS + o] = Wr2[o * 64 + kp];
        Ws[(64 + kp) * WSS + o] = Wl2[o * 64 + kp];
    }
    for (int i = tid; i < OUT; i += 256) { blsh[i] = bl[i]; gsh[i] = gam[i]; bsh[i] = bet[i]; }

    // stage activation tile [64 rows][256 k] = [X row | AGG row]
    int base = blockIdx.x * 64;
#pragma unroll
    for (int it = 0; it < 16; it++) {
        int linear = it * 256 + tid;
        int r = linear >> 6, q = linear & 63;
        int n = base + r;
        float4 v = make_float4(0.f, 0.f, 0.f, 0.f);
        if (n < N) v = (q < 32) ? X[n * 32 + q] : A[n * 32 + (q - 32)];
        As[r * 129 + q * 2]     = make_float2(v.x, v.y);
        As[r * 129 + q * 2 + 1] = make_float2(v.z, v.w);
    }
    __syncthreads();

    // register micro-tile: 4 rows x CPT cols, packed f32x2 accumulation over 128 k-pairs
    unsigned long long acc[4][CPT];
#pragma unroll
    for (int r = 0; r < 4; r++)
#pragma unroll
        for (int c = 0; c < CPT; c++) acc[r][c] = 0ull;

    const unsigned long long* As64 = reinterpret_cast<const unsigned long long*>(As);
    const int rbase = (tid >> 4) * 4 * 129;
    const int c0 = (tid & 15) * CPT;

#pragma unroll 4
    for (int kk = 0; kk < 128; kk++) {
        unsigned long long a0 = As64[rbase + kk];
        unsigned long long a1 = As64[rbase + 129 + kk];
        unsigned long long a2 = As64[rbase + 258 + kk];
        unsigned long long a3 = As64[rbase + 387 + kk];
        unsigned long long b[CPT];
        const ulonglong2* wp = reinterpret_cast<const ulonglong2*>(Ws + kk * WSS + c0);
#pragma unroll
        for (int c = 0; c < CPT / 2; c++) { ulonglong2 w = wp[c]; b[2 * c] = w.x; b[2 * c + 1] = w.y; }
#pragma unroll
        for (int c = 0; c < CPT; c++) {
            ffma2(acc[0][c], a0, b[c]);
            ffma2(acc[1][c], a1, b[c]);
            ffma2(acc[2][c], a2, b[c]);
            ffma2(acc[3][c], a3, b[c]);
        }
    }
    __syncthreads();   // all As reads done; reuse as Hs

    float* Hs = reinterpret_cast<float*>(As);
    constexpr int HSS = OUT + 1;
    {
        int ty = tid >> 4;
#pragma unroll
        for (int r = 0; r < 4; r++)
#pragma unroll
            for (int c = 0; c < CPT; c++) {
                union { unsigned long long u; float2 f; } cv;
                cv.u = acc[r][c];
                Hs[(ty * 4 + r) * HSS + c0 + c] = cv.f.x + cv.f.y + blsh[c0 + c];
            }
    }
    __syncthreads();

    // LayerNorm + ReLU: 4 threads per row
    int row = tid >> 2, part = tid & 3;
    constexpr int PC = OUT / 4;
    const float* hr = Hs + row * HSS;
    float s = 0.f, s2 = 0.f;
#pragma unroll
    for (int c = 0; c < PC; c++) { float h = hr[part * PC + c]; s += h; s2 += h * h; }
    s  += __shfl_xor_sync(0xffffffffu, s, 1);
    s2 += __shfl_xor_sync(0xffffffffu, s2, 1);
    s  += __shfl_xor_sync(0xffffffffu, s, 2);
    s2 += __shfl_xor_sync(0xffffffffu, s2, 2);
    float mu  = s * (1.0f / OUT);
    float var = s2 * (1.0f / OUT) - mu * mu;
    float rstd = rsqrtf(var + LN_EPS);
    int n = base + row;
    if (n < N) {
#pragma unroll
        for (int c = 0; c < PC; c += 4) {
            int cc = part * PC + c;
            float4 o;
            o.x = fmaxf((hr[cc + 0] - mu) * rstd * gsh[cc + 0] + bsh[cc + 0], 0.f);
            o.y = fmaxf((hr[cc + 1] - mu) * rstd * gsh[cc + 1] + bsh[cc + 1], 0.f);
            o.z = fmaxf((hr[cc + 2] - mu) * rstd * gsh[cc + 2] + bsh[cc + 2], 0.f);
            o.w = fmaxf((hr[cc + 3] - mu) * rstd * gsh[cc + 3] + bsh[cc + 3], 0.f);
            *reinterpret_cast<float4*>(&out[(long long)n * OUT + cc]) = o;
        }
    }
}

// ---------------- pooling: run-length local reduce (batch is sorted), then atomics ----------------
__global__ void k_pool(const float* __restrict__ h, const void* __restrict__ bat, int N) {
    int is64 = g_is64_b;
    int f = threadIdx.x & 63;
    int grp = (blockIdx.x * blockDim.x + threadIdx.x) >> 6;
    int ngroups = (gridDim.x * blockDim.x) >> 6;
    int chunk = (N + ngroups - 1) / ngroups;
    int lo = grp * chunk;
    int hi = min(N, lo + chunk);
    if (lo >= hi) return;
    int cur = (int)ld_idx(bat, lo, is64);
    float s = 0.f, m = 0.f;
    int cnt = 0;
    for (int n = lo; n < hi; n++) {
        int b = (int)ld_idx(bat, n, is64);
        if (b != cur) {
            atomicAdd(&g_psum[cur * 64 + f], s);
            atomicMax(&g_pmax[cur * 64 + f], __float_as_int(m));
            if (f == 0) atomicAdd(&g_pcnt[cur], cnt);
            s = 0.f; m = 0.f; cnt = 0; cur = b;
        }
        float v = h[(long long)n * 64 + f];
        s += v; m = fmaxf(m, v); cnt++;
    }
    atomicAdd(&g_psum[cur * 64 + f], s);
    atomicMax(&g_pmax[cur * 64 + f], __float_as_int(m));
    if (f == 0) atomicAdd(&g_pcnt[cur], cnt);
}

// ---------------- classifier head: one block per graph ----------------
__global__ void k_mlp(const float* __restrict__ cW1, const float* __restrict__ cb1,
                      const float* __restrict__ cW2, const float* __restrict__ cb2,
                      float* __restrict__ out, int C) {
    __shared__ float zs[128];
    __shared__ float hs[128];
    int g = blockIdx.x, tid = threadIdx.x;
    if (tid < 64) {
        float c = (float)g_pcnt[g];
        zs[tid] = g_psum[g * 64 + tid] / fmaxf(c, 1.f);
    } else {
        zs[tid] = __int_as_float(g_pmax[g * 64 + (tid - 64)]);
    }
    __syncthreads();
    float a = cb1[tid];
#pragma unroll 8
    for (int k = 0; k < 128; k++) a += zs[k] * cW1[tid * 128 + k];
    hs[tid] = fmaxf(a, 0.f);
    __syncthreads();
    if (tid < C) {
        float o = cb2[tid];
#pragma unroll 8
        for (int k = 0; k < 128; k++) o += hs[k] * cW2[tid * 128 + k];
        out[g * C + tid] = o;
    }
}

// ---------------- launch ----------------
extern "C" void kernel_launch(void* const* d_in, const int* in_sizes, int n_in,
                              void* d_out, int out_size) {
    const float4* x   = (const float4*)d_in[0];
    const void*   ei  = d_in[1];
    const void*   bat = d_in[2];
    const float *Wl0 = (const float*)d_in[3],  *bl0 = (const float*)d_in[4],  *Wr0 = (const float*)d_in[5];
    const float *g0  = (const float*)d_in[6],  *be0 = (const float*)d_in[7];
    const float *Wl1 = (const float*)d_in[8],  *bl1 = (const float*)d_in[9],  *Wr1 = (const float*)d_in[10];
    const float *g1  = (const float*)d_in[11], *be1 = (const float*)d_in[12];
    const float *Wl2 = (const float*)d_in[13], *bl2 = (const float*)d_in[14], *Wr2 = (const float*)d_in[15];
    const float *g2  = (const float*)d_in[16], *be2 = (const float*)d_in[17];
    const float *cW1 = (const float*)d_in[18], *cb1 = (const float*)d_in[19];
    const float *cW2 = (const float*)d_in[20], *cb2 = (const float*)d_in[21];

    int N = in_sizes[2];
    int E = in_sizes[1] / 2;
    int C = in_sizes[21];
    int G = out_size / C;

    void *p_agg, *p_h0, *p_h1, *p_h2;
    cudaGetSymbolAddress(&p_agg, g_agg);
    cudaGetSymbolAddress(&p_h0, g_h0);
    cudaGetSymbolAddress(&p_h1, g_h1);
    cudaGetSymbolAddress(&p_h2, g_h2);
    float4* agg = (float4*)p_agg;
    float4* h0  = (float4*)p_h0;
    float4* h1  = (float4*)p_h1;
    float4* h2  = (float4*)p_h2;

    const int SMEM128 = 128 * (128 + 2) * 8 + 64 * 129 * 8 + 3 * 128 * 4;  // 200704
    const int SMEM64  = 128 * (64 + 2) * 8 + 64 * 129 * 8 + 3 * 64 * 4;    // 134400
    cudaFuncSetAttribute(k_combine<128>, cudaFuncAttributeMaxDynamicSharedMemorySize, SMEM128);
    cudaFuncSetAttribute(k_combine<64>,  cudaFuncAttributeMaxDynamicSharedMemorySize, SMEM64);

    // dtype detection + CSR build (edges are layer-invariant)
    k_detect<<<1, 256>>>(ei, (long long)in_sizes[1], bat, (long long)in_sizes[2], N);
    int zgrid = (max(N, 4096) + 255) / 256;
    k_zero<<<zgrid, 256>>>(N);
    k_count<<<(E + 255) / 256, 256>>>(ei, E);
    k_scan<<<1, 1024>>>(N);
    k_fill<<<(E + 255) / 256, 256>>>(ei, E);

    int agrid = (N * 32 + 255) / 256;
    int cgrid = (N + 63) / 64;

    // layer 0
    k_agg<<<agrid, 256>>>(x, agg, N);
    k_combine<128><<<cgrid, 256, SMEM128>>>(x, agg, Wl0, Wr0, bl0, g0, be0, (float*)h0, N);
    // layer 1
    k_agg<<<agrid, 256>>>(h0, agg, N);
    k_combine<128><<<cgrid, 256, SMEM128>>>(h0, agg, Wl1, Wr1, bl1, g1, be1, (float*)h1, N);
    // layer 2
    k_agg<<<agrid, 256>>>(h1, agg, N);
    k_combine<64><<<cgrid, 256, SMEM64>>>(h1, agg, Wl2, Wr2, bl2, g2, be2, (float*)h2, N);

    // pooling + head
    k_pool<<<256, 256>>>((const float*)h2, bat, N);
    k_mlp<<<G, 128>>>(cW1, cb1, cW2, cb2, (float*)d_out, C);
}

// round 3
// speedup vs baseline: 1.6663x; 1.6663x over previous
#include <cuda_runtime.h>

#define MAXN 50000
#define MAXE 600000
#define LN_EPS 1e-5f

// ---------------- static device scratch (no runtime allocation) ----------------
__device__ int    g_is64_e, g_is64_b;
__device__ int    g_deg[MAXN];
__device__ int    g_rowstart[MAXN];
__device__ int    g_cursor[MAXN];
__device__ float  g_invdeg[MAXN];
__device__ int    g_bsum[256];
__device__ int    g_csr[MAXE];
__device__ float4 g_agg[MAXN * 32];   // [N,128] mean-aggregated features
__device__ float4 g_h0[MAXN * 32];    // layer0 out [N,128]
__device__ float4 g_h1[MAXN * 32];    // layer1 out [N,128]
__device__ float4 g_h2[MAXN * 16];    // layer2 out [N,64]
__device__ float  g_psum[64 * 64];
__device__ int    g_pmax[64 * 64];
__device__ int    g_pcnt[64];

__device__ __forceinline__ long long ld_idx(const void* p, long long i, int is64) {
    return is64 ? ((const long long*)p)[i] : (long long)((const int*)p)[i];
}

__device__ __forceinline__ void ffma2(unsigned long long& d, unsigned long long a, unsigned long long b) {
    asm("fma.rn.f32x2 %0, %1, %2, %0;" : "+l"(d) : "l"(a), "l"(b));
}

// ---------------- dtype width detection (int64 vs int32 indices) ----------------
__global__ void k_detect(const void* ei, long long ecnt, const void* bat, long long bcnt, int N) {
    __shared__ int ok_e, ok_b;
    int tid = threadIdx.x;
    if (tid == 0) { ok_e = 1; ok_b = 1; }
    __syncthreads();
    long long ne = ecnt / 2;   // int64 entries safely readable even if data is int32
    long long nb = bcnt / 2;
    long long ie = (ne - 1) * (long long)tid / 255;
    long long v = ((const long long*)ei)[ie];
    if (v < 0 || v >= (long long)N) atomicAnd(&ok_e, 0);
    long long ib = (nb - 1) * (long long)tid / 255;
    long long w = ((const long long*)bat)[ib];
    if (w < 0 || w >= 64) atomicAnd(&ok_b, 0);
    __syncthreads();
    if (tid == 0) { g_is64_e = ok_e; g_is64_b = ok_b; }
}

// ---------------- CSR build ----------------
__global__ void k_zero(int N) {
    int i = blockIdx.x * blockDim.x + threadIdx.x;
    if (i < N) g_deg[i] = 0;
    if (i < 64 * 64) { g_psum[i] = 0.f; g_pmax[i] = 0; }
    if (i < 64) g_pcnt[i] = 0;
}

__global__ void k_count(const void* ei, int E) {
    int is64 = g_is64_e;
    int e = blockIdx.x * blockDim.x + threadIdx.x;
    if (e >= E) return;
    int d = (int)ld_idx(ei, (long long)E + e, is64);
    atomicAdd(&g_deg[d], 1);
}

// multi-block scan, phase 1: per-block sums of degrees
__global__ void k_blocksum(int N) {
    __shared__ int ws[8];
    int tid = threadIdx.x, lane = tid & 31, wid = tid >> 5;
    int i = blockIdx.x * 256 + tid;
    int v = (i < N) ? g_deg[i] : 0;
    int s = v;
#pragma unroll
    for (int o = 16; o > 0; o >>= 1) s += __shfl_down_sync(0xffffffffu, s, o);
    if (lane == 0) ws[wid] = s;
    __syncthreads();
    if (wid == 0) {
        int t = (lane < 8) ? ws[lane] : 0;
#pragma unroll
        for (int o = 4; o > 0; o >>= 1) t += __shfl_down_sync(0xffffffffu, t, o);
        if (lane == 0) g_bsum[blockIdx.x] = t;
    }
}

// phase 2: single-block exclusive scan of <=256 block sums (in place)
__global__ void k_scanb(int nb) {
    __shared__ int ws[8];
    int tid = threadIdx.x, lane = tid & 31, wid = tid >> 5;
    int v = (tid < nb) ? g_bsum[tid] : 0;
    int x = v;
#pragma unroll
    for (int o = 1; o < 32; o <<= 1) { int y = __shfl_up_sync(0xffffffffu, x, o); if (lane >= o) x += y; }
    if (lane == 31) ws[wid] = x;
    __syncthreads();
    if (wid == 0 && lane < 8) {
        int w = ws[lane];
#pragma unroll
        for (int o = 1; o < 8; o <<= 1) { int y = __shfl_up_sync(0xffu, w, o); if (lane >= o) w += y; }
        ws[lane] = w;
    }
    __syncthreads();
    int incl = x + (wid ? ws[wid - 1] : 0);
    if (tid < nb) g_bsum[tid] = incl - v;   // exclusive
}

// phase 3: per-block scan + add block offset; fill rowstart/cursor/invdeg
__global__ void k_scatter(int N) {
    __shared__ int ws[8];
    int tid = threadIdx.x, lane = tid & 31, wid = tid >> 5;
    int i = blockIdx.x * 256 + tid;
    int v = (i < N) ? g_deg[i] : 0;
    int x = v;
#pragma unroll
    for (int o = 1; o < 32; o <<= 1) { int y = __shfl_up_sync(0xffffffffu, x, o); if (lane >= o) x += y; }
    if (lane == 31) ws[wid] = x;
    __syncthreads();
    if (wid == 0 && lane < 8) {
        int w = ws[lane];
#pragma unroll
        for (int o = 1; o < 8; o <<= 1) { int y = __shfl_up_sync(0xffu, w, o); if (lane >= o) w += y; }
        ws[lane] = w;
    }
    __syncthreads();
    if (i < N) {
        int excl = x - v + (wid ? ws[wid - 1] : 0) + g_bsum[blockIdx.x];
        g_rowstart[i] = excl;
        g_cursor[i] = excl;
        g_invdeg[i] = 1.0f / fmaxf((float)v, 1.0f);
    }
}

__global__ void k_fill(const void* ei, int E) {
    int is64 = g_is64_e;
    int e = blockIdx.x * blockDim.x + threadIdx.x;
    if (e >= E) return;
    int s = (int)ld_idx(ei, e, is64);
    int d = (int)ld_idx(ei, (long long)E + e, is64);
    int pos = atomicAdd(&g_cursor[d], 1);
    g_csr[pos] = s;
}

// ---------------- mean aggregation: one warp per node ----------------
__global__ void k_agg(const float4* __restrict__ feat, float4* __restrict__ agg, int N) {
    int node = (blockIdx.x * blockDim.x + threadIdx.x) >> 5;
    int lane = threadIdx.x & 31;
    if (node >= N) return;
    int start = g_rowstart[node], dg = g_deg[node];
    float4 a0 = make_float4(0.f, 0.f, 0.f, 0.f);
    float4 a1 = make_float4(0.f, 0.f, 0.f, 0.f);
    int j = 0;
    for (; j + 3 < dg; j += 4) {
        int s0 = g_csr[start + j];
        int s1 = g_csr[start + j + 1];
        int s2 = g_csr[start + j + 2];
        int s3 = g_csr[start + j + 3];
        float4 v0 = feat[s0 * 32 + lane];
        float4 v1 = feat[s1 * 32 + lane];
        float4 v2 = feat[s2 * 32 + lane];
        float4 v3 = feat[s3 * 32 + lane];
        a0.x += v0.x + v1.x; a0.y += v0.y + v1.y; a0.z += v0.z + v1.z; a0.w += v0.w + v1.w;
        a1.x += v2.x + v3.x; a1.y += v2.y + v3.y; a1.z += v2.z + v3.z; a1.w += v2.w + v3.w;
    }
    for (; j < dg; j++) {
        int s0 = g_csr[start + j];
        float4 v0 = feat[s0 * 32 + lane];
        a0.x += v0.x; a0.y += v0.y; a0.z += v0.z; a0.w += v0.w;
    }
    float inv = g_invdeg[node];
    float4 acc;
    acc.x = (a0.x + a1.x) * inv; acc.y = (a0.y + a1.y) * inv;
    acc.z = (a0.z + a1.z) * inv; acc.w = (a0.w + a1.w) * inv;
    agg[node * 32 + lane] = acc;
}

// ---------------- fused dual-GEMM + bias + LayerNorm + ReLU ----------------
// h[n,o] = sum_k X[n,k]*Wr[o,k] + sum_k AGG[n,k]*Wl[o,k] + bl[o]; LN over o; relu.
// Tile: 64 nodes x OUT cols, K=256 (X | AGG), f32x2 packed FMA.
// Thread column ownership: col(c) = 2*(tid&15) + 32*(c>>1) + (c&1) -> lanes 0-15
// load a CONTIGUOUS 256B strip of W per (kk,j): conflict-free LDS.128, upper
// half-warp broadcasts.
template <int OUT>
__global__ __launch_bounds__(256, 1) void k_combine(
    const float4* __restrict__ X, const float4* __restrict__ A,
    const float* __restrict__ Wl, const float* __restrict__ Wr,
    const float* __restrict__ bl, const float* __restrict__ gam, const float* __restrict__ bet,
    float* __restrict__ out, int N)
{
    constexpr int WSS = OUT + 4;   // float2 stride of W smem rows (row bytes multiple of 16)
    constexpr int CPT = OUT / 16;  // cols per thread
    constexpr int NJ  = CPT / 2;   // float4 W loads per kk
    extern __shared__ unsigned char smem[];
    float2* Ws = reinterpret_cast<float2*>(smem);            // [128][WSS] : (Wt[2kk][o], Wt[2kk+1][o])
    float2* As = Ws + 128 * WSS;                             // [64][129]  : (in[n][2kk], in[n][2kk+1])
    float* aux = reinterpret_cast<float*>(As + 64 * 129);
    float* blsh = aux;
    float* gsh  = aux + OUT;
    float* bsh  = aux + 2 * OUT;

    int tid = threadIdx.x;

    // stage weights: k<128 -> Wr (pairs with X), k>=128 -> Wl (pairs with AGG)
    const float2* Wr2 = reinterpret_cast<const float2*>(Wr);
    const float2* Wl2 = reinterpret_cast<const float2*>(Wl);
    for (int idx = tid; idx < OUT * 64; idx += 256) {
        int o = idx >> 6, kp = idx & 63;
        Ws[kp * WSS + o] = Wr2[o * 64 + kp];
        Ws[(64 + kp) * WSS + o] = Wl2[o * 64 + kp];
    }
    for (int i = tid; i < OUT; i += 256) { blsh[i] = bl[i]; gsh[i] = gam[i]; bsh[i] = bet[i]; }

    // stage activation tile [64 rows][256 k] = [X row | AGG row]
    int base = blockIdx.x * 64;
#pragma unroll
    for (int it = 0; it < 16; it++) {
        int linear = it * 256 + tid;
        int r = linear >> 6, q = linear & 63;
        int n = base + r;
        float4 v = make_float4(0.f, 0.f, 0.f, 0.f);
        if (n < N) v = (q < 32) ? X[n * 32 + q] : A[n * 32 + (q - 32)];
        As[r * 129 + q * 2]     = make_float2(v.x, v.y);
        As[r * 129 + q * 2 + 1] = make_float2(v.z, v.w);
    }
    __syncthreads();

    // register micro-tile: 4 rows x CPT cols, packed f32x2 accumulation over 128 k-pairs
    unsigned long long acc[4][CPT];
#pragma unroll
    for (int r = 0; r < 4; r++)
#pragma unroll
        for (int c = 0; c < CPT; c++) acc[r][c] = 0ull;

    const unsigned long long* As64 = reinterpret_cast<const unsigned long long*>(As);
    const int rbase = (tid >> 4) * 4 * 129;
    const int lane16 = tid & 15;

#pragma unroll 4
    for (int kk = 0; kk < 128; kk++) {
        unsigned long long a0 = As64[rbase + kk];
        unsigned long long a1 = As64[rbase + 129 + kk];
        unsigned long long a2 = As64[rbase + 258 + kk];
        unsigned long long a3 = As64[rbase + 387 + kk];
        unsigned long long b[CPT];
#pragma unroll
        for (int j = 0; j < NJ; j++) {
            // float2-index 2*lane16 + 32*j within W row kk: 16B-aligned, contiguous across lanes
            const ulonglong2* wp = reinterpret_cast<const ulonglong2*>(Ws + kk * WSS + 2 * lane16 + 32 * j);
            ulonglong2 w = *wp;
            b[2 * j] = w.x; b[2 * j + 1] = w.y;
        }
#pragma unroll
        for (int c = 0; c < CPT; c++) {
            ffma2(acc[0][c], a0, b[c]);
            ffma2(acc[1][c], a1, b[c]);
            ffma2(acc[2][c], a2, b[c]);
            ffma2(acc[3][c], a3, b[c]);
        }
    }
    __syncthreads();   // all As reads done; reuse as Hs

    float* Hs = reinterpret_cast<float*>(As);
    constexpr int HSS = OUT + 1;
    {
        int ty = tid >> 4;
#pragma unroll
        for (int r = 0; r < 4; r++)
#pragma unroll
            for (int c = 0; c < CPT; c++) {
                int col = 2 * lane16 + 32 * (c >> 1) + (c & 1);
                union { unsigned long long u; float2 f; } cv;
                cv.u = acc[r][c];
                Hs[(ty * 4 + r) * HSS + col] = cv.f.x + cv.f.y + blsh[col];
            }
    }
    __syncthreads();

    // LayerNorm + ReLU: 4 threads per row
    int row = tid >> 2, part = tid & 3;
    constexpr int PC = OUT / 4;
    const float* hr = Hs + row * HSS;
    float s = 0.f, s2 = 0.f;
#pragma unroll
    for (int c = 0; c < PC; c++) { float h = hr[part * PC + c]; s += h; s2 += h * h; }
    s  += __shfl_xor_sync(0xffffffffu, s, 1);
    s2 += __shfl_xor_sync(0xffffffffu, s2, 1);
    s  += __shfl_xor_sync(0xffffffffu, s, 2);
    s2 += __shfl_xor_sync(0xffffffffu, s2, 2);
    float mu  = s * (1.0f / OUT);
    float var = s2 * (1.0f / OUT) - mu * mu;
    float rstd = rsqrtf(var + LN_EPS);
    int n = base + row;
    if (n < N) {
#pragma unroll
        for (int c = 0; c < PC; c += 4) {
            int cc = part * PC + c;
            float4 o;
            o.x = fmaxf((hr[cc + 0] - mu) * rstd * gsh[cc + 0] + bsh[cc + 0], 0.f);
            o.y = fmaxf((hr[cc + 1] - mu) * rstd * gsh[cc + 1] + bsh[cc + 1], 0.f);
            o.z = fmaxf((hr[cc + 2] - mu) * rstd * gsh[cc + 2] + bsh[cc + 2], 0.f);
            o.w = fmaxf((hr[cc + 3] - mu) * rstd * gsh[cc + 3] + bsh[cc + 3], 0.f);
            *reinterpret_cast<float4*>(&out[(long long)n * OUT + cc]) = o;
        }
    }
}

// ---------------- pooling: run-length local reduce (batch is sorted), then atomics ----------------
__global__ void k_pool(const float* __restrict__ h, const void* __restrict__ bat, int N) {
    int is64 = g_is64_b;
    int f = threadIdx.x & 63;
    int grp = (blockIdx.x * blockDim.x + threadIdx.x) >> 6;
    int ngroups = (gridDim.x * blockDim.x) >> 6;
    int chunk = (N + ngroups - 1) / ngroups;
    int lo = grp * chunk;
    int hi = min(N, lo + chunk);
    if (lo >= hi) return;
    int cur = (int)ld_idx(bat, lo, is64);
    float s = 0.f, m = 0.f;
    int cnt = 0;
    for (int n = lo; n < hi; n++) {
        int b = (int)ld_idx(bat, n, is64);
        if (b != cur) {
            atomicAdd(&g_psum[cur * 64 + f], s);
            atomicMax(&g_pmax[cur * 64 + f], __float_as_int(m));
            if (f == 0) atomicAdd(&g_pcnt[cur], cnt);
            s = 0.f; m = 0.f; cnt = 0; cur = b;
        }
        float v = h[(long long)n * 64 + f];
        s += v; m = fmaxf(m, v); cnt++;
    }
    atomicAdd(&g_psum[cur * 64 + f], s);
    atomicMax(&g_pmax[cur * 64 + f], __float_as_int(m));
    if (f == 0) atomicAdd(&g_pcnt[cur], cnt);
}

// ---------------- classifier head: one block per graph ----------------
__global__ void k_mlp(const float* __restrict__ cW1, const float* __restrict__ cb1,
                      const float* __restrict__ cW2, const float* __restrict__ cb2,
                      float* __restrict__ out, int C) {
    __shared__ float zs[128];
    __shared__ float hs[128];
    int g = blockIdx.x, tid = threadIdx.x;
    if (tid < 64) {
        float c = (float)g_pcnt[g];
        zs[tid] = g_psum[g * 64 + tid] / fmaxf(c, 1.f);
    } else {
        zs[tid] = __int_as_float(g_pmax[g * 64 + (tid - 64)]);
    }
    __syncthreads();
    float a = cb1[tid];
#pragma unroll 8
    for (int k = 0; k < 128; k++) a += zs[k] * cW1[tid * 128 + k];
    hs[tid] = fmaxf(a, 0.f);
    __syncthreads();
    if (tid < C) {
        float o = cb2[tid];
#pragma unroll 8
        for (int k = 0; k < 128; k++) o += hs[k] * cW2[tid * 128 + k];
        out[g * C + tid] = o;
    }
}

// ---------------- launch ----------------
extern "C" void kernel_launch(void* const* d_in, const int* in_sizes, int n_in,
                              void* d_out, int out_size) {
    const float4* x   = (const float4*)d_in[0];
    const void*   ei  = d_in[1];
    const void*   bat = d_in[2];
    const float *Wl0 = (const float*)d_in[3],  *bl0 = (const float*)d_in[4],  *Wr0 = (const float*)d_in[5];
    const float *g0  = (const float*)d_in[6],  *be0 = (const float*)d_in[7];
    const float *Wl1 = (const float*)d_in[8],  *bl1 = (const float*)d_in[9],  *Wr1 = (const float*)d_in[10];
    const float *g1  = (const float*)d_in[11], *be1 = (const float*)d_in[12];
    const float *Wl2 = (const float*)d_in[13], *bl2 = (const float*)d_in[14], *Wr2 = (const float*)d_in[15];
    const float *g2  = (const float*)d_in[16], *be2 = (const float*)d_in[17];
    const float *cW1 = (const float*)d_in[18], *cb1 = (const float*)d_in[19];
    const float *cW2 = (const float*)d_in[20], *cb2 = (const float*)d_in[21];

    int N = in_sizes[2];
    int E = in_sizes[1] / 2;
    int C = in_sizes[21];
    int G = out_size / C;

    void *p_agg, *p_h0, *p_h1, *p_h2;
    cudaGetSymbolAddress(&p_agg, g_agg);
    cudaGetSymbolAddress(&p_h0, g_h0);
    cudaGetSymbolAddress(&p_h1, g_h1);
    cudaGetSymbolAddress(&p_h2, g_h2);
    float4* agg = (float4*)p_agg;
    float4* h0  = (float4*)p_h0;
    float4* h1  = (float4*)p_h1;
    float4* h2  = (float4*)p_h2;

    const int SMEM128 = 128 * (128 + 4) * 8 + 64 * 129 * 8 + 3 * 128 * 4;
    const int SMEM64  = 128 * (64 + 4) * 8 + 64 * 129 * 8 + 3 * 64 * 4;
    cudaFuncSetAttribute(k_combine<128>, cudaFuncAttributeMaxDynamicSharedMemorySize, SMEM128);
    cudaFuncSetAttribute(k_combine<64>,  cudaFuncAttributeMaxDynamicSharedMemorySize, SMEM64);

    int nb = (N + 255) / 256;   // <=256 blocks for N<=65536

    // dtype detection + CSR build (edges are layer-invariant)
    k_detect<<<1, 256>>>(ei, (long long)in_sizes[1], bat, (long long)in_sizes[2], N);
    int zgrid = (max(N, 4096) + 255) / 256;
    k_zero<<<zgrid, 256>>>(N);
    k_count<<<(E + 255) / 256, 256>>>(ei, E);
    k_blocksum<<<nb, 256>>>(N);
    k_scanb<<<1, 256>>>(nb);
    k_scatter<<<nb, 256>>>(N);
    k_fill<<<(E + 255) / 256, 256>>>(ei, E);

    int agrid = (N * 32 + 255) / 256;
    int cgrid = (N + 63) / 64;

    // layer 0
    k_agg<<<agrid, 256>>>(x, agg, N);
    k_combine<128><<<cgrid, 256, SMEM128>>>(x, agg, Wl0, Wr0, bl0, g0, be0, (float*)h0, N);
    // layer 1
    k_agg<<<agrid, 256>>>(h0, agg, N);
    k_combine<128><<<cgrid, 256, SMEM128>>>(h0, agg, Wl1, Wr1, bl1, g1, be1, (float*)h1, N);
    // layer 2
    k_agg<<<agrid, 256>>>(h1, agg, N);
    k_combine<64><<<cgrid, 256, SMEM64>>>(h1, agg, Wl2, Wr2, bl2, g2, be2, (float*)h2, N);

    // pooling + head
    k_pool<<<256, 256>>>((const float*)h2, bat, N);
    k_mlp<<<G, 128>>>(cW1, cb1, cW2, cb2, (float*)d_out, C);
}